// round 1
// baseline (speedup 1.0000x reference)
#include <cuda_runtime.h>
#include <cuda_bf16.h>
#include <cfloat>

// ---------------------------------------------------------------------------
// Problem: EmbeddingBag mean||max (B bags over T tokens, D=128) then Linear
//   feature_seq : int32 [T]
//   offset_seq  : int32 [B]  (sorted bag starts, offs[0]==0)
//   W           : f32   [VOCAB, 128]
//   L           : f32   [TYPES=128, 256]
//   out         : f32   [B, 128] = concat(mean, max) @ L^T
// ---------------------------------------------------------------------------

#define D 128
#define K2 256            // 2*D
#define MAX_B 8192

// scratch for the concat(mean, max) matrix [B, 256]
__device__ float g_men[MAX_B * K2];

// ---------------------------------------------------------------------------
// Kernel 1: per-bag gather + mean/max reduce.
// One block per bag, 128 threads = one per embedding column.
// ---------------------------------------------------------------------------
__global__ void __launch_bounds__(D) bag_reduce_kernel(
    const int* __restrict__ feat,
    const int* __restrict__ offs,
    const float* __restrict__ W,
    int T, int B)
{
    const int b = blockIdx.x;
    const int d = threadIdx.x;

    const int start = offs[b];
    const int end   = (b == B - 1) ? T : offs[b + 1];
    const int cnt   = end - start;

    float s = 0.0f;
    float m = -FLT_MAX;

    int t = start;
    // unroll x4: 4 gathered rows in flight per thread (MLP=4)
    for (; t + 4 <= end; t += 4) {
        const int f0 = __ldg(&feat[t + 0]);
        const int f1 = __ldg(&feat[t + 1]);
        const int f2 = __ldg(&feat[t + 2]);
        const int f3 = __ldg(&feat[t + 3]);
        const float v0 = __ldg(&W[(long)f0 * D + d]);
        const float v1 = __ldg(&W[(long)f1 * D + d]);
        const float v2 = __ldg(&W[(long)f2 * D + d]);
        const float v3 = __ldg(&W[(long)f3 * D + d]);
        s += v0; s += v1; s += v2; s += v3;
        m = fmaxf(m, fmaxf(fmaxf(v0, v1), fmaxf(v2, v3)));
    }
    for (; t < end; ++t) {
        const int f = __ldg(&feat[t]);
        const float v = __ldg(&W[(long)f * D + d]);
        s += v;
        m = fmaxf(m, v);
    }

    const float mean = s / fmaxf((float)cnt, 1.0f);
    if (cnt == 0) m = 0.0f;   // empty bag -> max is 0 per reference

    g_men[(long)b * K2 + d]     = mean;
    g_men[(long)b * K2 + D + d] = m;
}

// ---------------------------------------------------------------------------
// Kernel 2: C[B,128] = men[B,256] @ L[128,256]^T
// Tiled SGEMM: BM=64, BN=128 (all cols), BK=32. 256 threads (16x16),
// each thread owns a 4x8 register tile. Smem tiles stored K-major
// (transposed) so inner-loop reads are vectorized float4 and conflict-free.
// ---------------------------------------------------------------------------
#define BM 64
#define BN 128
#define BK 32

__global__ void __launch_bounds__(256) men_gemm_kernel(
    const float* __restrict__ L,
    float* __restrict__ out,
    int B)
{
    __shared__ float As[BK][BM];   // As[kk][row]
    __shared__ float Ls[BK][BN];   // Ls[kk][col]

    const int tid = threadIdx.x;
    const int tx  = tid % 16;      // col group: 8 cols each
    const int ty  = tid / 16;      // row group: 4 rows each
    const int brow0 = blockIdx.x * BM;

    float acc[4][8];
#pragma unroll
    for (int i = 0; i < 4; ++i)
#pragma unroll
        for (int j = 0; j < 8; ++j) acc[i][j] = 0.0f;

    for (int k0 = 0; k0 < K2; k0 += BK) {
        // --- load A tile: 64 rows x 32 k -> 512 float4 slots, 2 per thread
#pragma unroll
        for (int q = 0; q < 2; ++q) {
            const int slot = tid * 2 + q;          // 0..511
            const int r  = slot >> 3;              // 0..63
            const int kq = (slot & 7) * 4;         // 0,4,...,28
            const float4 v = *reinterpret_cast<const float4*>(
                &g_men[(long)(brow0 + r) * K2 + k0 + kq]);
            As[kq + 0][r] = v.x;
            As[kq + 1][r] = v.y;
            As[kq + 2][r] = v.z;
            As[kq + 3][r] = v.w;
        }
        // --- load L tile: 128 cols x 32 k -> 1024 float4 slots, 4 per thread
#pragma unroll
        for (int q = 0; q < 4; ++q) {
            const int slot = tid * 4 + q;          // 0..1023
            const int j  = slot >> 3;              // 0..127 (output col / L row)
            const int kq = (slot & 7) * 4;
            const float4 v = *reinterpret_cast<const float4*>(
                &L[(long)j * K2 + k0 + kq]);
            Ls[kq + 0][j] = v.x;
            Ls[kq + 1][j] = v.y;
            Ls[kq + 2][j] = v.z;
            Ls[kq + 3][j] = v.w;
        }
        __syncthreads();

#pragma unroll
        for (int kk = 0; kk < BK; ++kk) {
            const float4 a  = *reinterpret_cast<const float4*>(&As[kk][ty * 4]);
            const float4 b0 = *reinterpret_cast<const float4*>(&Ls[kk][tx * 8]);
            const float4 b1 = *reinterpret_cast<const float4*>(&Ls[kk][tx * 8 + 4]);
            const float av[4] = {a.x, a.y, a.z, a.w};
            const float bv[8] = {b0.x, b0.y, b0.z, b0.w, b1.x, b1.y, b1.z, b1.w};
#pragma unroll
            for (int i = 0; i < 4; ++i)
#pragma unroll
                for (int j = 0; j < 8; ++j)
                    acc[i][j] = fmaf(av[i], bv[j], acc[i][j]);
        }
        __syncthreads();
    }

    // --- write back 4x8 tile
#pragma unroll
    for (int i = 0; i < 4; ++i) {
        const int row = brow0 + ty * 4 + i;
        float* o = &out[(long)row * BN + tx * 8];
        float4 w0 = make_float4(acc[i][0], acc[i][1], acc[i][2], acc[i][3]);
        float4 w1 = make_float4(acc[i][4], acc[i][5], acc[i][6], acc[i][7]);
        *reinterpret_cast<float4*>(o)     = w0;
        *reinterpret_cast<float4*>(o + 4) = w1;
    }
}

// ---------------------------------------------------------------------------
extern "C" void kernel_launch(void* const* d_in, const int* in_sizes, int n_in,
                              void* d_out, int out_size)
{
    const int*   feat = (const int*)d_in[0];
    const int*   offs = (const int*)d_in[1];
    const float* W    = (const float*)d_in[2];
    const float* L    = (const float*)d_in[3];
    float*       out  = (float*)d_out;

    const int T = in_sizes[0];
    const int B = in_sizes[1];

    bag_reduce_kernel<<<B, D>>>(feat, offs, W, T, B);
    men_gemm_kernel<<<B / BM, 256>>>(L, out, B);
}

// round 3
// speedup vs baseline: 1.2603x; 1.2603x over previous
#include <cuda_runtime.h>
#include <cuda_bf16.h>
#include <cfloat>
#include <cstdint>

// ---------------------------------------------------------------------------
// EmbeddingBag mean||max (B=8192 bags over T=409600 tokens, D=128) + Linear
//   feature_seq : int32 [T]
//   offset_seq  : int32 [B]   (sorted bag starts, offs[0]==0)
//   W           : f32   [VOCAB, 128]
//   L           : f32   [128, 256]
//   out         : f32   [B, 128] = concat(mean, max) @ L^T
// ---------------------------------------------------------------------------

#define D 128
#define K2 256
#define MAX_B 8192

__device__ __align__(16) float g_men[MAX_B * K2];   // [B, 256] scratch

// ============================================================================
// Kernel 1: warp-per-bag gather + mean/max reduce.
// Lane l handles columns [4l, 4l+4) via float4; one LDG.128 per lane = one
// 512B row per warp. Unroll x4 for MLP=4.
// ============================================================================
__global__ void __launch_bounds__(256) bag_reduce_kernel(
    const int* __restrict__ feat,
    const int* __restrict__ offs,
    const float* __restrict__ W,
    int T, int B)
{
    const int bag  = blockIdx.x * 8 + (threadIdx.x >> 5);
    const int lane = threadIdx.x & 31;
    if (bag >= B) return;

    const int start = offs[bag];
    const int end   = (bag == B - 1) ? T : offs[bag + 1];
    const int cnt   = end - start;

    const float4* __restrict__ Wv = (const float4*)W;   // row stride = 32 float4

    float4 s = make_float4(0.f, 0.f, 0.f, 0.f);
    float4 m = make_float4(-FLT_MAX, -FLT_MAX, -FLT_MAX, -FLT_MAX);

    int t = start;
    for (; t + 4 <= end; t += 4) {
        const int f0 = __ldg(&feat[t + 0]);
        const int f1 = __ldg(&feat[t + 1]);
        const int f2 = __ldg(&feat[t + 2]);
        const int f3 = __ldg(&feat[t + 3]);
        const float4 v0 = __ldg(&Wv[f0 * 32 + lane]);
        const float4 v1 = __ldg(&Wv[f1 * 32 + lane]);
        const float4 v2 = __ldg(&Wv[f2 * 32 + lane]);
        const float4 v3 = __ldg(&Wv[f3 * 32 + lane]);
        s.x += v0.x + v1.x + v2.x + v3.x;
        s.y += v0.y + v1.y + v2.y + v3.y;
        s.z += v0.z + v1.z + v2.z + v3.z;
        s.w += v0.w + v1.w + v2.w + v3.w;
        m.x = fmaxf(m.x, fmaxf(fmaxf(v0.x, v1.x), fmaxf(v2.x, v3.x)));
        m.y = fmaxf(m.y, fmaxf(fmaxf(v0.y, v1.y), fmaxf(v2.y, v3.y)));
        m.z = fmaxf(m.z, fmaxf(fmaxf(v0.z, v1.z), fmaxf(v2.z, v3.z)));
        m.w = fmaxf(m.w, fmaxf(fmaxf(v0.w, v1.w), fmaxf(v2.w, v3.w)));
    }
    for (; t < end; ++t) {
        const int f = __ldg(&feat[t]);
        const float4 v = __ldg(&Wv[f * 32 + lane]);
        s.x += v.x; s.y += v.y; s.z += v.z; s.w += v.w;
        m.x = fmaxf(m.x, v.x); m.y = fmaxf(m.y, v.y);
        m.z = fmaxf(m.z, v.z); m.w = fmaxf(m.w, v.w);
    }

    const float inv = 1.0f / fmaxf((float)cnt, 1.0f);
    float4 mean = make_float4(s.x * inv, s.y * inv, s.z * inv, s.w * inv);
    if (cnt == 0) m = make_float4(0.f, 0.f, 0.f, 0.f);

    float4* mp = (float4*)g_men;                 // row stride = 64 float4
    mp[bag * 64 + lane]      = mean;             // cols [0,128)
    mp[bag * 64 + 32 + lane] = m;                // cols [128,256)
}

// ============================================================================
// Kernel 2: C[8192,128] = men[8192,256] @ L[128,256]^T
// via mma.sync.aligned.m16n8k8 tf32 (HMMA path, valid on sm_100 target).
// BM=64, BN=128 (full), BK=32. 8 warps in 2x4; warp tile 32x32 = 2x4 mma tiles.
// ============================================================================
#define BM 64
#define BN 128
#define BK 32
#define APAD 4
#define LDA (BK + APAD)    // 36, row addr stride keeps lanes on distinct banks

__device__ __forceinline__ uint32_t f2tf32(float f) {
    uint32_t r;
    asm("cvt.rna.tf32.f32 %0, %1;" : "=r"(r) : "f"(f));
    return r;
}

__device__ __forceinline__ void mma_tf32(float c[4],
                                         uint32_t a0, uint32_t a1, uint32_t a2, uint32_t a3,
                                         uint32_t b0, uint32_t b1) {
    asm volatile(
        "mma.sync.aligned.m16n8k8.row.col.f32.tf32.tf32.f32 "
        "{%0,%1,%2,%3}, {%4,%5,%6,%7}, {%8,%9}, {%0,%1,%2,%3};"
        : "+f"(c[0]), "+f"(c[1]), "+f"(c[2]), "+f"(c[3])
        : "r"(a0), "r"(a1), "r"(a2), "r"(a3), "r"(b0), "r"(b1));
}

__global__ void __launch_bounds__(256) men_gemm_kernel(
    const float* __restrict__ L,
    float* __restrict__ out,
    int B)
{
    __shared__ uint32_t As[BM * LDA];   // men tile, tf32, [row][k] stride 36
    __shared__ uint32_t Bs[BN * LDA];   // L tile,   tf32, [n][k]   stride 36

    const int tid  = threadIdx.x;
    const int wid  = tid >> 5;
    const int lane = tid & 31;
    const int wr   = wid >> 2;          // warp row 0..1 (32 rows each)
    const int wc   = wid & 3;           // warp col 0..3 (32 cols each)
    const int gp   = lane >> 2;         // groupID 0..7
    const int tg   = lane & 3;          // thread in group 0..3
    const int brow0 = blockIdx.x * BM;

    float acc[2][4][4];
#pragma unroll
    for (int i = 0; i < 2; ++i)
#pragma unroll
        for (int j = 0; j < 4; ++j)
#pragma unroll
            for (int v = 0; v < 4; ++v) acc[i][j][v] = 0.0f;

    for (int k0 = 0; k0 < K2; k0 += BK) {
        // --- A tile: 64 rows x 32 k = 512 float4 slots, 2 per thread
#pragma unroll
        for (int q = 0; q < 2; ++q) {
            const int slot = tid * 2 + q;     // 0..511
            const int r  = slot >> 3;         // 0..63
            const int kq = (slot & 7) * 4;
            const float4 v = *reinterpret_cast<const float4*>(
                &g_men[(brow0 + r) * K2 + k0 + kq]);
            uint32_t* p = &As[r * LDA + kq];
            p[0] = f2tf32(v.x); p[1] = f2tf32(v.y);
            p[2] = f2tf32(v.z); p[3] = f2tf32(v.w);
        }
        // --- B tile: 128 n-rows x 32 k = 1024 float4 slots, 4 per thread
#pragma unroll
        for (int q = 0; q < 4; ++q) {
            const int slot = tid * 4 + q;     // 0..1023
            const int n  = slot >> 3;         // 0..127
            const int kq = (slot & 7) * 4;
            const float4 v = *reinterpret_cast<const float4*>(
                &L[n * K2 + k0 + kq]);
            uint32_t* p = &Bs[n * LDA + kq];
            p[0] = f2tf32(v.x); p[1] = f2tf32(v.y);
            p[2] = f2tf32(v.z); p[3] = f2tf32(v.w);
        }
        __syncthreads();

#pragma unroll
        for (int ks = 0; ks < BK; ks += 8) {
            // B fragments for 4 n-tiles
            uint32_t bf[4][2];
#pragma unroll
            for (int nt = 0; nt < 4; ++nt) {
                const int n = wc * 32 + nt * 8 + gp;
                bf[nt][0] = Bs[n * LDA + ks + tg];
                bf[nt][1] = Bs[n * LDA + ks + tg + 4];
            }
            // A fragments for 2 m-tiles, then FMA across n-tiles
#pragma unroll
            for (int mt = 0; mt < 2; ++mt) {
                const int r = wr * 32 + mt * 16 + gp;
                const uint32_t a0 = As[r * LDA + ks + tg];
                const uint32_t a1 = As[(r + 8) * LDA + ks + tg];
                const uint32_t a2 = As[r * LDA + ks + tg + 4];
                const uint32_t a3 = As[(r + 8) * LDA + ks + tg + 4];
#pragma unroll
                for (int nt = 0; nt < 4; ++nt)
                    mma_tf32(acc[mt][nt], a0, a1, a2, a3, bf[nt][0], bf[nt][1]);
            }
        }
        __syncthreads();
    }

    // --- epilogue: c0/c1 -> (row, 2tg..2tg+1), c2/c3 -> (row+8, ...)
#pragma unroll
    for (int mt = 0; mt < 2; ++mt) {
#pragma unroll
        for (int nt = 0; nt < 4; ++nt) {
            const int row = brow0 + wr * 32 + mt * 16 + gp;
            const int col = wc * 32 + nt * 8 + tg * 2;
            float2* o0 = reinterpret_cast<float2*>(&out[row * BN + col]);
            float2* o1 = reinterpret_cast<float2*>(&out[(row + 8) * BN + col]);
            *o0 = make_float2(acc[mt][nt][0], acc[mt][nt][1]);
            *o1 = make_float2(acc[mt][nt][2], acc[mt][nt][3]);
        }
    }
}

// ---------------------------------------------------------------------------
extern "C" void kernel_launch(void* const* d_in, const int* in_sizes, int n_in,
                              void* d_out, int out_size)
{
    const int*   feat = (const int*)d_in[0];
    const int*   offs = (const int*)d_in[1];
    const float* W    = (const float*)d_in[2];
    const float* L    = (const float*)d_in[3];
    float*       out  = (float*)d_out;

    const int T = in_sizes[0];
    const int B = in_sizes[1];

    bag_reduce_kernel<<<(B + 7) / 8, 256>>>(feat, offs, W, T, B);
    men_gemm_kernel<<<B / BM, 256>>>(L, out, B);
}

// round 4
// speedup vs baseline: 2.0731x; 1.6450x over previous
#include <cuda_runtime.h>
#include <cuda_bf16.h>
#include <cfloat>
#include <cstdint>

// ---------------------------------------------------------------------------
// EmbeddingBag mean||max (B=8192 bags over T=409600 tokens, D=128) + Linear
//   feature_seq : int32 [T]
//   offset_seq  : int32 [B]   (sorted bag starts, offs[0]==0)
//   W           : f32   [VOCAB, 128]
//   L           : f32   [128, 256]
//   out         : f32   [B, 128] = concat(mean, max) @ L^T
// ---------------------------------------------------------------------------

#define D 128
#define K2 256
#define MAX_B 8192

__device__ __align__(16) float g_men[MAX_B * K2];   // [B, 256] scratch

// ============================================================================
// Kernel 1: block-per-bag, 8 warps split the bag's tokens (stride 8),
// smem combine. Lane l covers columns [4l, 4l+4) via one float4 per row.
// Kills the serial tail of the largest bag (~480 tokens -> 8-way parallel).
// ============================================================================
__global__ void __launch_bounds__(256) bag_reduce_kernel(
    const int* __restrict__ feat,
    const int* __restrict__ offs,
    const float* __restrict__ W,
    int T, int B)
{
    const int bag  = blockIdx.x;
    const int w    = threadIdx.x >> 5;
    const int lane = threadIdx.x & 31;

    const int start = offs[bag];
    const int end   = (bag == B - 1) ? T : offs[bag + 1];
    const int cnt   = end - start;

    const float4* __restrict__ Wv = (const float4*)W;   // row stride = 32 float4

    float4 s = make_float4(0.f, 0.f, 0.f, 0.f);
    float4 m = make_float4(-FLT_MAX, -FLT_MAX, -FLT_MAX, -FLT_MAX);

    int t = start + w;
    // unrolled x4: tokens t, t+8, t+16, t+24 in flight (MLP=4 per warp, x8 warps)
    for (; t + 24 < end; t += 32) {
        const int f0 = __ldg(&feat[t +  0]);
        const int f1 = __ldg(&feat[t +  8]);
        const int f2 = __ldg(&feat[t + 16]);
        const int f3 = __ldg(&feat[t + 24]);
        const float4 v0 = __ldg(&Wv[f0 * 32 + lane]);
        const float4 v1 = __ldg(&Wv[f1 * 32 + lane]);
        const float4 v2 = __ldg(&Wv[f2 * 32 + lane]);
        const float4 v3 = __ldg(&Wv[f3 * 32 + lane]);
        s.x += v0.x + v1.x + v2.x + v3.x;
        s.y += v0.y + v1.y + v2.y + v3.y;
        s.z += v0.z + v1.z + v2.z + v3.z;
        s.w += v0.w + v1.w + v2.w + v3.w;
        m.x = fmaxf(m.x, fmaxf(fmaxf(v0.x, v1.x), fmaxf(v2.x, v3.x)));
        m.y = fmaxf(m.y, fmaxf(fmaxf(v0.y, v1.y), fmaxf(v2.y, v3.y)));
        m.z = fmaxf(m.z, fmaxf(fmaxf(v0.z, v1.z), fmaxf(v2.z, v3.z)));
        m.w = fmaxf(m.w, fmaxf(fmaxf(v0.w, v1.w), fmaxf(v2.w, v3.w)));
    }
    for (; t < end; t += 8) {
        const int f = __ldg(&feat[t]);
        const float4 v = __ldg(&Wv[f * 32 + lane]);
        s.x += v.x; s.y += v.y; s.z += v.z; s.w += v.w;
        m.x = fmaxf(m.x, v.x); m.y = fmaxf(m.y, v.y);
        m.z = fmaxf(m.z, v.z); m.w = fmaxf(m.w, v.w);
    }

    __shared__ float4 Ss[8][32];
    __shared__ float4 Sm[8][32];
    Ss[w][lane] = s;
    Sm[w][lane] = m;
    __syncthreads();

    if (threadIdx.x < 32) {
        float4 rs = Ss[0][lane];
        float4 rm = Sm[0][lane];
#pragma unroll
        for (int i = 1; i < 8; ++i) {
            const float4 a = Ss[i][lane];
            const float4 b = Sm[i][lane];
            rs.x += a.x; rs.y += a.y; rs.z += a.z; rs.w += a.w;
            rm.x = fmaxf(rm.x, b.x); rm.y = fmaxf(rm.y, b.y);
            rm.z = fmaxf(rm.z, b.z); rm.w = fmaxf(rm.w, b.w);
        }
        const float inv = 1.0f / fmaxf((float)cnt, 1.0f);
        float4 mean = make_float4(rs.x * inv, rs.y * inv, rs.z * inv, rs.w * inv);
        if (cnt == 0) rm = make_float4(0.f, 0.f, 0.f, 0.f);

        float4* mp = (float4*)g_men;                 // row stride = 64 float4
        mp[bag * 64 + lane]      = mean;             // cols [0,128)
        mp[bag * 64 + 32 + lane] = rm;               // cols [128,256)
    }
}

// ============================================================================
// Kernel 2: C[8192,128] = men[8192,256] @ L[128,256]^T
// mma.sync m16n8k8 tf32. BM=64, BN=64, BK=32, 256 blocks (grid 128x2).
// 8 warps as 4x2; warp tile 16x32 = 1x4 mma tiles.
// ============================================================================
#define BM 64
#define BN 64
#define BK 32
#define APAD 4
#define LDA (BK + APAD)    // 36

__device__ __forceinline__ uint32_t f2tf32(float f) {
    uint32_t r;
    asm("cvt.rna.tf32.f32 %0, %1;" : "=r"(r) : "f"(f));
    return r;
}

__device__ __forceinline__ void mma_tf32(float c[4],
                                         uint32_t a0, uint32_t a1, uint32_t a2, uint32_t a3,
                                         uint32_t b0, uint32_t b1) {
    asm volatile(
        "mma.sync.aligned.m16n8k8.row.col.f32.tf32.tf32.f32 "
        "{%0,%1,%2,%3}, {%4,%5,%6,%7}, {%8,%9}, {%0,%1,%2,%3};"
        : "+f"(c[0]), "+f"(c[1]), "+f"(c[2]), "+f"(c[3])
        : "r"(a0), "r"(a1), "r"(a2), "r"(a3), "r"(b0), "r"(b1));
}

__global__ void __launch_bounds__(256) men_gemm_kernel(
    const float* __restrict__ L,
    float* __restrict__ out,
    int B)
{
    __shared__ uint32_t As[BM * LDA];   // men tile, tf32
    __shared__ uint32_t Bs[BN * LDA];   // L tile,   tf32

    const int tid  = threadIdx.x;
    const int wid  = tid >> 5;
    const int lane = tid & 31;
    const int wr   = wid >> 1;          // warp row 0..3 (16 rows each)
    const int wc   = wid & 1;           // warp col 0..1 (32 cols each)
    const int gp   = lane >> 2;         // groupID 0..7
    const int tg   = lane & 3;          // thread in group 0..3
    const int brow0 = blockIdx.x * BM;
    const int bcol0 = blockIdx.y * BN;

    float acc[4][4];
#pragma unroll
    for (int j = 0; j < 4; ++j)
#pragma unroll
        for (int v = 0; v < 4; ++v) acc[j][v] = 0.0f;

    for (int k0 = 0; k0 < K2; k0 += BK) {
        // --- A tile: 64 rows x 32 k = 512 float4 slots, 2 per thread
#pragma unroll
        for (int q = 0; q < 2; ++q) {
            const int slot = tid * 2 + q;     // 0..511
            const int r  = slot >> 3;
            const int kq = (slot & 7) * 4;
            const float4 v = *reinterpret_cast<const float4*>(
                &g_men[(brow0 + r) * K2 + k0 + kq]);
            uint32_t* p = &As[r * LDA + kq];
            p[0] = f2tf32(v.x); p[1] = f2tf32(v.y);
            p[2] = f2tf32(v.z); p[3] = f2tf32(v.w);
        }
        // --- B tile: 64 n-rows x 32 k = 512 float4 slots, 2 per thread
#pragma unroll
        for (int q = 0; q < 2; ++q) {
            const int slot = tid * 2 + q;
            const int n  = slot >> 3;
            const int kq = (slot & 7) * 4;
            const float4 v = *reinterpret_cast<const float4*>(
                &L[(bcol0 + n) * K2 + k0 + kq]);
            uint32_t* p = &Bs[n * LDA + kq];
            p[0] = f2tf32(v.x); p[1] = f2tf32(v.y);
            p[2] = f2tf32(v.z); p[3] = f2tf32(v.w);
        }
        __syncthreads();

#pragma unroll
        for (int ks = 0; ks < BK; ks += 8) {
            uint32_t bf[4][2];
#pragma unroll
            for (int nt = 0; nt < 4; ++nt) {
                const int n = wc * 32 + nt * 8 + gp;
                bf[nt][0] = Bs[n * LDA + ks + tg];
                bf[nt][1] = Bs[n * LDA + ks + tg + 4];
            }
            const int r = wr * 16 + gp;
            const uint32_t a0 = As[r * LDA + ks + tg];
            const uint32_t a1 = As[(r + 8) * LDA + ks + tg];
            const uint32_t a2 = As[r * LDA + ks + tg + 4];
            const uint32_t a3 = As[(r + 8) * LDA + ks + tg + 4];
#pragma unroll
            for (int nt = 0; nt < 4; ++nt)
                mma_tf32(acc[nt], a0, a1, a2, a3, bf[nt][0], bf[nt][1]);
        }
        __syncthreads();
    }

    // --- epilogue
#pragma unroll
    for (int nt = 0; nt < 4; ++nt) {
        const int row = brow0 + wr * 16 + gp;
        const int col = bcol0 + wc * 32 + nt * 8 + tg * 2;
        float2* o0 = reinterpret_cast<float2*>(&out[row * 128 + col]);
        float2* o1 = reinterpret_cast<float2*>(&out[(row + 8) * 128 + col]);
        *o0 = make_float2(acc[nt][0], acc[nt][1]);
        *o1 = make_float2(acc[nt][2], acc[nt][3]);
    }
}

// ---------------------------------------------------------------------------
extern "C" void kernel_launch(void* const* d_in, const int* in_sizes, int n_in,
                              void* d_out, int out_size)
{
    const int*   feat = (const int*)d_in[0];
    const int*   offs = (const int*)d_in[1];
    const float* W    = (const float*)d_in[2];
    const float* L    = (const float*)d_in[3];
    float*       out  = (float*)d_out;

    const int T = in_sizes[0];
    const int B = in_sizes[1];

    bag_reduce_kernel<<<B, 256>>>(feat, offs, W, T, B);

    dim3 grid(B / BM, 128 / BN);
    men_gemm_kernel<<<grid, 256>>>(L, out, B);
}

// round 5
// speedup vs baseline: 2.1208x; 1.0230x over previous
#include <cuda_runtime.h>
#include <cuda_bf16.h>
#include <cfloat>
#include <cstdint>

// ---------------------------------------------------------------------------
// EmbeddingBag mean||max (B=8192 bags over T=409600 tokens, D=128) + Linear
//   feature_seq : int32 [T]
//   offset_seq  : int32 [B]   (sorted bag starts, offs[0]==0)
//   W           : f32   [VOCAB, 128]
//   L           : f32   [128, 256]
//   out         : f32   [B, 128] = concat(mean, max) @ L^T
// ---------------------------------------------------------------------------

#define D 128
#define K2 256
#define MAX_B 8192

__device__ __align__(16) float g_men[MAX_B * K2];   // [B, 256] scratch

// ============================================================================
// Kernel 1: block-per-bag, 8 warps; warp w takes a CONTIGUOUS chunk of
// ceil(cnt/8) tokens so the x4-unrolled (MLP=4) path is the common case.
// Lane l covers columns [4l,4l+4) via one float4 per row.
// ============================================================================
__global__ void __launch_bounds__(256) bag_reduce_kernel(
    const int* __restrict__ feat,
    const int* __restrict__ offs,
    const float* __restrict__ W,
    int T, int B)
{
    const int bag  = blockIdx.x;
    const int w    = threadIdx.x >> 5;
    const int lane = threadIdx.x & 31;

    const int start = offs[bag];
    const int end   = (bag == B - 1) ? T : offs[bag + 1];
    const int cnt   = end - start;

    const float4* __restrict__ Wv = (const float4*)W;   // row stride = 32 float4

    float4 s = make_float4(0.f, 0.f, 0.f, 0.f);
    float4 m = make_float4(-FLT_MAX, -FLT_MAX, -FLT_MAX, -FLT_MAX);

    const int chunk = (cnt + 7) >> 3;
    const int cs = start + w * chunk;
    const int ce = min(cs + chunk, end);

    int t = cs;
    for (; t + 4 <= ce; t += 4) {
        const int f0 = __ldg(&feat[t + 0]);
        const int f1 = __ldg(&feat[t + 1]);
        const int f2 = __ldg(&feat[t + 2]);
        const int f3 = __ldg(&feat[t + 3]);
        const float4 v0 = __ldg(&Wv[f0 * 32 + lane]);
        const float4 v1 = __ldg(&Wv[f1 * 32 + lane]);
        const float4 v2 = __ldg(&Wv[f2 * 32 + lane]);
        const float4 v3 = __ldg(&Wv[f3 * 32 + lane]);
        s.x += v0.x + v1.x + v2.x + v3.x;
        s.y += v0.y + v1.y + v2.y + v3.y;
        s.z += v0.z + v1.z + v2.z + v3.z;
        s.w += v0.w + v1.w + v2.w + v3.w;
        m.x = fmaxf(m.x, fmaxf(fmaxf(v0.x, v1.x), fmaxf(v2.x, v3.x)));
        m.y = fmaxf(m.y, fmaxf(fmaxf(v0.y, v1.y), fmaxf(v2.y, v3.y)));
        m.z = fmaxf(m.z, fmaxf(fmaxf(v0.z, v1.z), fmaxf(v2.z, v3.z)));
        m.w = fmaxf(m.w, fmaxf(fmaxf(v0.w, v1.w), fmaxf(v2.w, v3.w)));
    }
    for (; t < ce; ++t) {
        const int f = __ldg(&feat[t]);
        const float4 v = __ldg(&Wv[f * 32 + lane]);
        s.x += v.x; s.y += v.y; s.z += v.z; s.w += v.w;
        m.x = fmaxf(m.x, v.x); m.y = fmaxf(m.y, v.y);
        m.z = fmaxf(m.z, v.z); m.w = fmaxf(m.w, v.w);
    }

    __shared__ float4 Ss[8][32];
    __shared__ float4 Sm[8][32];
    Ss[w][lane] = s;
    Sm[w][lane] = m;
    __syncthreads();

    if (threadIdx.x < 32) {
        float4 rs = Ss[0][lane];
        float4 rm = Sm[0][lane];
#pragma unroll
        for (int i = 1; i < 8; ++i) {
            const float4 a = Ss[i][lane];
            const float4 b = Sm[i][lane];
            rs.x += a.x; rs.y += a.y; rs.z += a.z; rs.w += a.w;
            rm.x = fmaxf(rm.x, b.x); rm.y = fmaxf(rm.y, b.y);
            rm.z = fmaxf(rm.z, b.z); rm.w = fmaxf(rm.w, b.w);
        }
        const float inv = 1.0f / fmaxf((float)cnt, 1.0f);
        float4 mean = make_float4(rs.x * inv, rs.y * inv, rs.z * inv, rs.w * inv);
        if (cnt == 0) rm = make_float4(0.f, 0.f, 0.f, 0.f);

        float4* mp = (float4*)g_men;                 // row stride = 64 float4
        mp[bag * 64 + lane]      = mean;             // cols [0,128)
        mp[bag * 64 + 32 + lane] = rm;               // cols [128,256)
    }
}

// ============================================================================
// Kernel 2: C[8192,128] = men[8192,256] @ L[128,256]^T, mma.sync m16n8k8 tf32.
// Single-phase: the ENTIRE K=256 lives in smem (A 64x256 + B 128x256 tf32,
// ~195KB). One bulk load (48 independent float4/thread), one sync, then 32
// uninterrupted mma k-steps. grid = 128 blocks = one wave, 1 block/SM.
// ============================================================================
#define BM 64
#define BN 128
#define LDK (K2 + 4)       // 260: pad keeps fragment LDS conflict-free

__device__ __forceinline__ uint32_t f2tf32(float f) {
    uint32_t r;
    asm("cvt.rna.tf32.f32 %0, %1;" : "=r"(r) : "f"(f));
    return r;
}

__device__ __forceinline__ void mma_tf32(float c[4],
                                         uint32_t a0, uint32_t a1, uint32_t a2, uint32_t a3,
                                         uint32_t b0, uint32_t b1) {
    asm volatile(
        "mma.sync.aligned.m16n8k8.row.col.f32.tf32.tf32.f32 "
        "{%0,%1,%2,%3}, {%4,%5,%6,%7}, {%8,%9}, {%0,%1,%2,%3};"
        : "+f"(c[0]), "+f"(c[1]), "+f"(c[2]), "+f"(c[3])
        : "r"(a0), "r"(a1), "r"(a2), "r"(a3), "r"(b0), "r"(b1));
}

#define GEMM_SMEM_BYTES ((BM * LDK + BN * LDK) * 4)   // 199680

__global__ void __launch_bounds__(256) men_gemm_kernel(
    const float* __restrict__ L,
    float* __restrict__ out,
    int B)
{
    extern __shared__ uint32_t sh[];
    uint32_t* As = sh;                 // [64][260] tf32
    uint32_t* Bs = sh + BM * LDK;      // [128][260] tf32

    const int tid  = threadIdx.x;
    const int wid  = tid >> 5;
    const int lane = tid & 31;
    const int wr   = wid >> 2;          // 0..1  (32 rows each)
    const int wc   = wid & 3;           // 0..3  (32 cols each)
    const int gp   = lane >> 2;
    const int tg   = lane & 3;
    const int brow0 = blockIdx.x * BM;

    // --- bulk load + tf32 convert: A 64x64 float4, B 128x64 float4
    for (int idx = tid; idx < BM * 64; idx += 256) {
        const int r = idx >> 6;
        const int q = idx & 63;
        const float4 v = *reinterpret_cast<const float4*>(
            &g_men[(brow0 + r) * K2 + q * 4]);
        uint32_t* p = &As[r * LDK + q * 4];
        p[0] = f2tf32(v.x); p[1] = f2tf32(v.y);
        p[2] = f2tf32(v.z); p[3] = f2tf32(v.w);
    }
    for (int idx = tid; idx < BN * 64; idx += 256) {
        const int n = idx >> 6;
        const int q = idx & 63;
        const float4 v = *reinterpret_cast<const float4*>(&L[n * K2 + q * 4]);
        uint32_t* p = &Bs[n * LDK + q * 4];
        p[0] = f2tf32(v.x); p[1] = f2tf32(v.y);
        p[2] = f2tf32(v.z); p[3] = f2tf32(v.w);
    }
    __syncthreads();

    float acc[2][4][4];
#pragma unroll
    for (int i = 0; i < 2; ++i)
#pragma unroll
        for (int j = 0; j < 4; ++j)
#pragma unroll
            for (int v = 0; v < 4; ++v) acc[i][j][v] = 0.0f;

#pragma unroll 8
    for (int ks = 0; ks < K2; ks += 8) {
        uint32_t bf[4][2];
#pragma unroll
        for (int nt = 0; nt < 4; ++nt) {
            const int n = wc * 32 + nt * 8 + gp;
            bf[nt][0] = Bs[n * LDK + ks + tg];
            bf[nt][1] = Bs[n * LDK + ks + tg + 4];
        }
#pragma unroll
        for (int mt = 0; mt < 2; ++mt) {
            const int r = wr * 32 + mt * 16 + gp;
            const uint32_t a0 = As[r * LDK + ks + tg];
            const uint32_t a1 = As[(r + 8) * LDK + ks + tg];
            const uint32_t a2 = As[r * LDK + ks + tg + 4];
            const uint32_t a3 = As[(r + 8) * LDK + ks + tg + 4];
#pragma unroll
            for (int nt = 0; nt < 4; ++nt)
                mma_tf32(acc[mt][nt], a0, a1, a2, a3, bf[nt][0], bf[nt][1]);
        }
    }

    // --- epilogue
#pragma unroll
    for (int mt = 0; mt < 2; ++mt) {
#pragma unroll
        for (int nt = 0; nt < 4; ++nt) {
            const int row = brow0 + wr * 32 + mt * 16 + gp;
            const int col = wc * 32 + nt * 8 + tg * 2;
            float2* o0 = reinterpret_cast<float2*>(&out[row * BN + col]);
            float2* o1 = reinterpret_cast<float2*>(&out[(row + 8) * BN + col]);
            *o0 = make_float2(acc[mt][nt][0], acc[mt][nt][1]);
            *o1 = make_float2(acc[mt][nt][2], acc[mt][nt][3]);
        }
    }
}

// ---------------------------------------------------------------------------
extern "C" void kernel_launch(void* const* d_in, const int* in_sizes, int n_in,
                              void* d_out, int out_size)
{
    const int*   feat = (const int*)d_in[0];
    const int*   offs = (const int*)d_in[1];
    const float* W    = (const float*)d_in[2];
    const float* L    = (const float*)d_in[3];
    float*       out  = (float*)d_out;

    const int T = in_sizes[0];
    const int B = in_sizes[1];

    cudaFuncSetAttribute(men_gemm_kernel,
                         cudaFuncAttributeMaxDynamicSharedMemorySize,
                         GEMM_SMEM_BYTES);

    bag_reduce_kernel<<<B, 256>>>(feat, offs, W, T, B);
    men_gemm_kernel<<<B / BM, 256, GEMM_SMEM_BYTES>>>(L, out, B);
}